// round 1
// baseline (speedup 1.0000x reference)
#include <cuda_runtime.h>
#include <math.h>

#define Dv   512
#define Nn   8192
#define K1   2560    // 5*D  (Agg_0..3, x)
#define QK   2048    // 4*D  (q,k,v,skip)

// ---- static scratch (no allocations allowed) ----
__device__ float g_H0[(size_t)Nn * K1];     // 80 MB  [N, 5D]
__device__ float g_ho[(size_t)Nn * Dv];     // 16 MB  [N, D]
__device__ float g_qkvs[(size_t)Nn * QK];   // 64 MB  [N, 4, D] = q|k|v|skip

__device__ __forceinline__ int lower_bound_i(const int* __restrict__ a, int n, int key) {
    int lo = 0, hi = n;
    while (lo < hi) { int m = (lo + hi) >> 1; if (a[m] < key) lo = m + 1; else hi = m; }
    return lo;
}

// ============================================================
// Kernel 1: per-node per-relation neighbor mean -> H0 [N, 5D]
// Edges are sorted by dst (reference builds them that way).
// ============================================================
__global__ __launch_bounds__(128) void agg_kernel(
    const float* __restrict__ x,
    const int*   __restrict__ src,
    const int*   __restrict__ dst,
    const int*   __restrict__ et,
    int E)
{
    int i = blockIdx.x;        // node
    int t = threadIdx.x;       // 0..127
    __shared__ int s_lo, s_nE;
    __shared__ int s_src[32], s_rel[32];
    __shared__ int s_cnt[4];

    if (t == 0) {
        int lo = lower_bound_i(dst, E, i);
        int hi = lower_bound_i(dst, E, i + 1);
        s_lo = lo;
        int n = hi - lo; if (n > 32) n = 32;
        s_nE = n;
    }
    if (t < 4) s_cnt[t] = 0;
    __syncthreads();
    int nE = s_nE, lo = s_lo;
    if (t < nE) {
        s_src[t] = src[lo + t];
        int r = et[lo + t];
        s_rel[t] = r;
        atomicAdd(&s_cnt[r], 1);
    }
    __syncthreads();

    int d0 = t * 4;
    float4 a0 = {0,0,0,0}, a1 = a0, a2 = a0, a3 = a0;
    for (int e = 0; e < nE; e++) {
        int s = s_src[e];
        float4 v = *reinterpret_cast<const float4*>(x + (size_t)s * Dv + d0);
        int r = s_rel[e];
        if (r == 0)      { a0.x += v.x; a0.y += v.y; a0.z += v.z; a0.w += v.w; }
        else if (r == 1) { a1.x += v.x; a1.y += v.y; a1.z += v.z; a1.w += v.w; }
        else if (r == 2) { a2.x += v.x; a2.y += v.y; a2.z += v.z; a2.w += v.w; }
        else             { a3.x += v.x; a3.y += v.y; a3.z += v.z; a3.w += v.w; }
    }
    float i0 = 1.f / fmaxf((float)s_cnt[0], 1.f);
    float i1 = 1.f / fmaxf((float)s_cnt[1], 1.f);
    float i2 = 1.f / fmaxf((float)s_cnt[2], 1.f);
    float i3 = 1.f / fmaxf((float)s_cnt[3], 1.f);
    float* H = g_H0 + (size_t)i * K1;
    a0.x*=i0; a0.y*=i0; a0.z*=i0; a0.w*=i0;
    a1.x*=i1; a1.y*=i1; a1.z*=i1; a1.w*=i1;
    a2.x*=i2; a2.y*=i2; a2.z*=i2; a2.w*=i2;
    a3.x*=i3; a3.y*=i3; a3.z*=i3; a3.w*=i3;
    *reinterpret_cast<float4*>(H + 0*Dv + d0) = a0;
    *reinterpret_cast<float4*>(H + 1*Dv + d0) = a1;
    *reinterpret_cast<float4*>(H + 2*Dv + d0) = a2;
    *reinterpret_cast<float4*>(H + 3*Dv + d0) = a3;
    float4 xv = *reinterpret_cast<const float4*>(x + (size_t)i * Dv + d0);
    *reinterpret_cast<float4*>(H + 4*Dv + d0) = xv;
}

// ============================================================
// Kernel 2: ho = H0 [8192x2560] @ [W_rel;W_root] [2560x512] + b
// 128x128x16 tile, 8x8 per thread, 256 threads
// ============================================================
__global__ __launch_bounds__(256) void gemm_rgcn(
    const float* __restrict__ Wrel,   // [2048, 512] (R*D rows)
    const float* __restrict__ Wroot,  // [512, 512]
    const float* __restrict__ bias)   // [512]
{
    const float* A = g_H0;
    float* C = g_ho;
    const int K = K1, Nc = Dv;
    __shared__ float As[16][128];
    __shared__ float Bs[16][128];
    int tid = threadIdx.x;
    int n0 = blockIdx.x * 128;
    int m0 = blockIdx.y * 128;
    int tx = tid & 15, ty = tid >> 4;
    float acc[8][8] = {};

    for (int k0 = 0; k0 < K; k0 += 16) {
        #pragma unroll
        for (int s = 0; s < 2; s++) {
            int v = tid * 2 + s;           // 0..511
            int row = v >> 2;              // 0..127
            int kq = (v & 3) * 4;          // 0,4,8,12
            float4 av = *reinterpret_cast<const float4*>(A + (size_t)(m0 + row) * K + k0 + kq);
            As[kq+0][row] = av.x; As[kq+1][row] = av.y;
            As[kq+2][row] = av.z; As[kq+3][row] = av.w;
        }
        #pragma unroll
        for (int s = 0; s < 2; s++) {
            int v = tid * 2 + s;
            int r = v >> 5;                // 0..15
            int cq = (v & 31) * 4;         // 0..124
            int kk = k0 + r;
            const float* bp = (kk < 2048) ? (Wrel + (size_t)kk * Dv)
                                          : (Wroot + (size_t)(kk - 2048) * Dv);
            *reinterpret_cast<float4*>(&Bs[r][cq]) =
                *reinterpret_cast<const float4*>(bp + n0 + cq);
        }
        __syncthreads();
        #pragma unroll
        for (int kk = 0; kk < 16; kk++) {
            float a[8], b[8];
            *(float4*)&a[0] = *(float4*)&As[kk][ty*8];
            *(float4*)&a[4] = *(float4*)&As[kk][ty*8+4];
            *(float4*)&b[0] = *(float4*)&Bs[kk][tx*8];
            *(float4*)&b[4] = *(float4*)&Bs[kk][tx*8+4];
            #pragma unroll
            for (int ii = 0; ii < 8; ii++)
                #pragma unroll
                for (int jj = 0; jj < 8; jj++)
                    acc[ii][jj] += a[ii] * b[jj];
        }
        __syncthreads();
    }
    #pragma unroll
    for (int ii = 0; ii < 8; ii++) {
        int row = m0 + ty*8 + ii;
        #pragma unroll
        for (int jj = 0; jj < 8; jj += 4) {
            int col = n0 + tx*8 + jj;
            float4 o;
            o.x = acc[ii][jj+0] + bias[col+0];
            o.y = acc[ii][jj+1] + bias[col+1];
            o.z = acc[ii][jj+2] + bias[col+2];
            o.w = acc[ii][jj+3] + bias[col+3];
            *reinterpret_cast<float4*>(C + (size_t)row * Nc + col) = o;
        }
    }
}

// ============================================================
// Kernel 3: [q|k|v|skip] = ho [8192x512] @ W [512x2048] + b
// column-block selects which weight matrix (each 128-col tile
// lies inside one 512-wide weight since 512 % 128 == 0).
// ============================================================
__global__ __launch_bounds__(256) void gemm_qkvs(
    const float* __restrict__ Wq, const float* __restrict__ Wk,
    const float* __restrict__ Wv, const float* __restrict__ Ws,
    const float* __restrict__ bq, const float* __restrict__ bk,
    const float* __restrict__ bv, const float* __restrict__ bs)
{
    const float* A = g_ho;
    float* C = g_qkvs;
    const int K = Dv, Nc = QK;
    __shared__ float As[16][128];
    __shared__ float Bs[16][128];
    int tid = threadIdx.x;
    int n0 = blockIdx.x * 128;        // global col 0..2047
    int m0 = blockIdx.y * 128;
    int wsel = n0 >> 9;
    const float* W  = (wsel == 0) ? Wq : (wsel == 1) ? Wk : (wsel == 2) ? Wv : Ws;
    const float* bb = (wsel == 0) ? bq : (wsel == 1) ? bk : (wsel == 2) ? bv : bs;
    int bc0 = n0 & 511;
    int tx = tid & 15, ty = tid >> 4;
    float acc[8][8] = {};

    for (int k0 = 0; k0 < K; k0 += 16) {
        #pragma unroll
        for (int s = 0; s < 2; s++) {
            int v = tid * 2 + s;
            int row = v >> 2;
            int kq = (v & 3) * 4;
            float4 av = *reinterpret_cast<const float4*>(A + (size_t)(m0 + row) * K + k0 + kq);
            As[kq+0][row] = av.x; As[kq+1][row] = av.y;
            As[kq+2][row] = av.z; As[kq+3][row] = av.w;
        }
        #pragma unroll
        for (int s = 0; s < 2; s++) {
            int v = tid * 2 + s;
            int r = v >> 5;
            int cq = (v & 31) * 4;
            int kk = k0 + r;
            *reinterpret_cast<float4*>(&Bs[r][cq]) =
                *reinterpret_cast<const float4*>(W + (size_t)kk * Dv + bc0 + cq);
        }
        __syncthreads();
        #pragma unroll
        for (int kk = 0; kk < 16; kk++) {
            float a[8], b[8];
            *(float4*)&a[0] = *(float4*)&As[kk][ty*8];
            *(float4*)&a[4] = *(float4*)&As[kk][ty*8+4];
            *(float4*)&b[0] = *(float4*)&Bs[kk][tx*8];
            *(float4*)&b[4] = *(float4*)&Bs[kk][tx*8+4];
            #pragma unroll
            for (int ii = 0; ii < 8; ii++)
                #pragma unroll
                for (int jj = 0; jj < 8; jj++)
                    acc[ii][jj] += a[ii] * b[jj];
        }
        __syncthreads();
    }
    #pragma unroll
    for (int ii = 0; ii < 8; ii++) {
        int row = m0 + ty*8 + ii;
        #pragma unroll
        for (int jj = 0; jj < 8; jj += 4) {
            int bc = bc0 + tx*8 + jj;
            float4 o;
            o.x = acc[ii][jj+0] + bb[bc+0];
            o.y = acc[ii][jj+1] + bb[bc+1];
            o.z = acc[ii][jj+2] + bb[bc+2];
            o.w = acc[ii][jj+3] + bb[bc+3];
            *reinterpret_cast<float4*>(C + (size_t)row * Nc + n0 + tx*8 + jj) = o;
        }
    }
}

// ============================================================
// Kernel 4: per-node attention softmax + skip + leaky + residual + LN
// ============================================================
__global__ __launch_bounds__(256) void attn_kernel(
    const float* __restrict__ x,
    const int*   __restrict__ src,
    const int*   __restrict__ dst,
    int E,
    const float* __restrict__ gamma,
    const float* __restrict__ beta,
    float* __restrict__ out)
{
    int i = blockIdx.x;
    int t = threadIdx.x;     // 0..255
    __shared__ float q_s[512];
    __shared__ float logit[32];
    __shared__ float alpha[32];
    __shared__ int   s_src[32];
    __shared__ int   s_lo, s_nE;
    __shared__ float red1[8], red2[8];
    __shared__ float s_mu, s_rstd;
    const float* qkvs = g_qkvs;

    if (t == 0) {
        int lo = lower_bound_i(dst, E, i);
        int hi = lower_bound_i(dst, E, i + 1);
        s_lo = lo; int n = hi - lo; if (n > 32) n = 32; s_nE = n;
    }
    __syncthreads();
    int nE = s_nE, lo = s_lo;
    q_s[t]       = qkvs[(size_t)i * QK + t];
    q_s[t + 256] = qkvs[(size_t)i * QK + t + 256];
    if (t < nE) s_src[t] = src[lo + t];
    __syncthreads();

    int wid = t >> 5, lane = t & 31;
    for (int e = wid; e < nE; e += 8) {
        const float* kp = qkvs + (size_t)s_src[e] * QK + 512;
        float sum = 0.f;
        #pragma unroll
        for (int c = 0; c < 4; c++) {
            int d = c * 128 + lane * 4;
            float4 qa = *(const float4*)&q_s[d];
            float4 kb = *(const float4*)(kp + d);
            sum += qa.x*kb.x + qa.y*kb.y + qa.z*kb.z + qa.w*kb.w;
        }
        #pragma unroll
        for (int o = 16; o; o >>= 1) sum += __shfl_xor_sync(0xffffffffu, sum, o);
        if (lane == 0) logit[e] = sum * 0.04419417382415922f; // 1/sqrt(512)
    }
    __syncthreads();
    if (t == 0) {
        float mx = -INFINITY;
        for (int e = 0; e < nE; e++) mx = fmaxf(mx, logit[e]);
        if (nE == 0 || !isfinite(mx)) mx = 0.f;
        float den = 0.f;
        for (int e = 0; e < nE; e++) { float ex = expf(logit[e] - mx); alpha[e] = ex; den += ex; }
        float inv = 1.f / fmaxf(den, 1e-16f);
        for (int e = 0; e < nE; e++) alpha[e] *= inv;
    }
    __syncthreads();

    int d0 = t * 2;
    float acc0 = 0.f, acc1 = 0.f;
    for (int e = 0; e < nE; e++) {
        float a = alpha[e];
        float2 v = *(const float2*)(qkvs + (size_t)s_src[e] * QK + 1024 + d0);
        acc0 += a * v.x; acc1 += a * v.y;
    }
    float2 sk = *(const float2*)(qkvs + (size_t)i * QK + 1536 + d0);
    float h0 = acc0 + sk.x, h1 = acc1 + sk.y;
    h0 = h0 > 0.f ? h0 : 0.01f * h0;
    h1 = h1 > 0.f ? h1 : 0.01f * h1;
    float2 xv = *(const float2*)(x + (size_t)i * Dv + d0);
    float o0 = xv.x + h0, o1 = xv.y + h1;

    float s1 = o0 + o1, s2 = o0*o0 + o1*o1;
    #pragma unroll
    for (int o = 16; o; o >>= 1) {
        s1 += __shfl_xor_sync(0xffffffffu, s1, o);
        s2 += __shfl_xor_sync(0xffffffffu, s2, o);
    }
    if (lane == 0) { red1[wid] = s1; red2[wid] = s2; }
    __syncthreads();
    if (t == 0) {
        float S1 = 0.f, S2 = 0.f;
        #pragma unroll
        for (int w = 0; w < 8; w++) { S1 += red1[w]; S2 += red2[w]; }
        float mu = S1 / 512.f;
        float var = S2 / 512.f - mu * mu;
        s_mu = mu; s_rstd = rsqrtf(var + 1e-5f);
    }
    __syncthreads();
    float mu = s_mu, rs = s_rstd;
    float2 ov;
    ov.x = (o0 - mu) * rs * gamma[d0]     + beta[d0];
    ov.y = (o1 - mu) * rs * gamma[d0 + 1] + beta[d0 + 1];
    *(float2*)(out + (size_t)i * Dv + d0) = ov;
}

// scalar loss output (always 0 in eval path)
__global__ void tail_kernel(float* out, int out_size) {
    int idx = Nn * Dv + threadIdx.x;
    if (idx < out_size) out[idx] = 0.f;
}

extern "C" void kernel_launch(void* const* d_in, const int* in_sizes, int n_in,
                              void* d_out, int out_size) {
    const float* x     = (const float*)d_in[0];
    const int*   ei    = (const int*)  d_in[1];
    const int*   et    = (const int*)  d_in[2];
    const float* Wrel  = (const float*)d_in[3];
    const float* Wroot = (const float*)d_in[4];
    const float* brg   = (const float*)d_in[5];
    const float* Wq    = (const float*)d_in[6];
    const float* bq    = (const float*)d_in[7];
    const float* Wk    = (const float*)d_in[8];
    const float* bk    = (const float*)d_in[9];
    const float* Wv    = (const float*)d_in[10];
    const float* bv    = (const float*)d_in[11];
    const float* Wsk   = (const float*)d_in[12];
    const float* bsk   = (const float*)d_in[13];
    const float* gamma = (const float*)d_in[14];
    const float* beta  = (const float*)d_in[15];
    float* out = (float*)d_out;

    int E = in_sizes[2];
    const int* src = ei;
    const int* dst = ei + E;

    agg_kernel<<<Nn, 128>>>(x, src, dst, et, E);
    gemm_rgcn<<<dim3(Dv / 128, Nn / 128), 256>>>(Wrel, Wroot, brg);
    gemm_qkvs<<<dim3(QK / 128, Nn / 128), 256>>>(Wq, Wk, Wv, Wsk, bq, bk, bv, bsk);
    attn_kernel<<<Nn, 256>>>(x, src, dst, E, gamma, beta, out);
    if (out_size > Nn * Dv) tail_kernel<<<1, 256>>>(out, out_size);
}

// round 5
// speedup vs baseline: 2.3465x; 2.3465x over previous
#include <cuda_runtime.h>
#include <math.h>
#include <stdint.h>

#define Dv   512
#define Nn   8192
#define K1   2560    // 5*D  (Agg_0..3, x)
#define QK   2048    // 4*D  (q,k,v,skip)

// ---- static scratch (no allocations allowed) ----
__device__ float g_H0[(size_t)Nn * K1];     // 80 MB  [N, 5D]
__device__ float g_ho[(size_t)Nn * Dv];     // 16 MB  [N, D]
__device__ float g_qkvs[(size_t)Nn * QK];   // 64 MB  [N, 4, D] = q|k|v|skip

__device__ __forceinline__ int lower_bound_i(const int* __restrict__ a, int n, int key) {
    int lo = 0, hi = n;
    while (lo < hi) { int m = (lo + hi) >> 1; if (a[m] < key) lo = m + 1; else hi = m; }
    return lo;
}

__device__ __forceinline__ float tf32r(float x) {
    uint32_t y;
    asm("cvt.rna.tf32.f32 %0, %1;" : "=r"(y) : "f"(x));
    return __uint_as_float(y);
}

__device__ __forceinline__ void mma8(float* d, const uint32_t* a, const uint32_t* b) {
    asm volatile(
        "mma.sync.aligned.m16n8k8.row.col.f32.tf32.tf32.f32 "
        "{%0,%1,%2,%3}, {%4,%5,%6,%7}, {%8,%9}, {%0,%1,%2,%3};"
        : "+f"(d[0]), "+f"(d[1]), "+f"(d[2]), "+f"(d[3])
        : "r"(a[0]), "r"(a[1]), "r"(a[2]), "r"(a[3]), "r"(b[0]), "r"(b[1]));
}

// ============================================================
// Kernel 1: per-node per-relation neighbor mean -> H0 [N, 5D]
// ============================================================
__global__ __launch_bounds__(128) void agg_kernel(
    const float* __restrict__ x,
    const int*   __restrict__ src,
    const int*   __restrict__ dst,
    const int*   __restrict__ et,
    int E)
{
    int i = blockIdx.x;
    int t = threadIdx.x;
    __shared__ int s_lo, s_nE;
    __shared__ int s_src[32], s_rel[32];
    __shared__ int s_cnt[4];

    if (t == 0) {
        int lo = lower_bound_i(dst, E, i);
        int hi = lower_bound_i(dst, E, i + 1);
        s_lo = lo;
        int n = hi - lo; if (n > 32) n = 32;
        s_nE = n;
    }
    if (t < 4) s_cnt[t] = 0;
    __syncthreads();
    int nE = s_nE, lo = s_lo;
    if (t < nE) {
        s_src[t] = src[lo + t];
        int r = et[lo + t];
        s_rel[t] = r;
        atomicAdd(&s_cnt[r], 1);
    }
    __syncthreads();

    int d0 = t * 4;
    float4 a0 = {0,0,0,0}, a1 = a0, a2 = a0, a3 = a0;
    for (int e = 0; e < nE; e++) {
        int s = s_src[e];
        float4 v = *reinterpret_cast<const float4*>(x + (size_t)s * Dv + d0);
        int r = s_rel[e];
        if (r == 0)      { a0.x += v.x; a0.y += v.y; a0.z += v.z; a0.w += v.w; }
        else if (r == 1) { a1.x += v.x; a1.y += v.y; a1.z += v.z; a1.w += v.w; }
        else if (r == 2) { a2.x += v.x; a2.y += v.y; a2.z += v.z; a2.w += v.w; }
        else             { a3.x += v.x; a3.y += v.y; a3.z += v.z; a3.w += v.w; }
    }
    float i0 = 1.f / fmaxf((float)s_cnt[0], 1.f);
    float i1 = 1.f / fmaxf((float)s_cnt[1], 1.f);
    float i2 = 1.f / fmaxf((float)s_cnt[2], 1.f);
    float i3 = 1.f / fmaxf((float)s_cnt[3], 1.f);
    float* H = g_H0 + (size_t)i * K1;
    a0.x*=i0; a0.y*=i0; a0.z*=i0; a0.w*=i0;
    a1.x*=i1; a1.y*=i1; a1.z*=i1; a1.w*=i1;
    a2.x*=i2; a2.y*=i2; a2.z*=i2; a2.w*=i2;
    a3.x*=i3; a3.y*=i3; a3.z*=i3; a3.w*=i3;
    *reinterpret_cast<float4*>(H + 0*Dv + d0) = a0;
    *reinterpret_cast<float4*>(H + 1*Dv + d0) = a1;
    *reinterpret_cast<float4*>(H + 2*Dv + d0) = a2;
    *reinterpret_cast<float4*>(H + 3*Dv + d0) = a3;
    float4 xv = *reinterpret_cast<const float4*>(x + (size_t)i * Dv + d0);
    *reinterpret_cast<float4*>(H + 4*Dv + d0) = xv;
}

// ============================================================
// TF32 tensor-core GEMM tiles: 128x128x32, 8 warps (2x4),
// warp tile 64x32 via m16n8k8 mma.
// As layout [m][k], lead 36 (frag reads bank-conflict-free).
// Bs layout [k][n], lead 132 (frag reads bank-conflict-free).
// ============================================================
#define LDA 36
#define LDB 132

// Kernel 2: ho = H0 [8192x2560] @ [W_rel;W_root] [2560x512] + b
__global__ __launch_bounds__(256) void gemm_rgcn(
    const float* __restrict__ Wrel,   // [2048, 512]
    const float* __restrict__ Wroot,  // [512, 512]
    const float* __restrict__ bias)   // [512]
{
    __shared__ float As[128 * LDA];
    __shared__ float Bs[32 * LDB];
    const float* A = g_H0;
    float* C = g_ho;
    const int K = K1;
    int tid = threadIdx.x;
    int n0 = blockIdx.x * 128, m0 = blockIdx.y * 128;
    int wid = tid >> 5, lane = tid & 31;
    int wr = wid >> 2, wc = wid & 3;
    int g = lane >> 2, tig = lane & 3;
    float acc[4][4][4] = {};
    float4 ra[4], rb[4];

    #pragma unroll
    for (int s = 0; s < 4; s++) {
        int idx = tid + 256 * s;
        int m = idx >> 3, kq = (idx & 7) * 4;
        ra[s] = *(const float4*)(A + (size_t)(m0 + m) * K + kq);
    }
    #pragma unroll
    for (int s = 0; s < 4; s++) {
        int idx = tid + 256 * s;
        int k = idx >> 5, n4 = (idx & 31) * 4;
        rb[s] = *(const float4*)(Wrel + (size_t)k * Dv + n0 + n4);
    }

    const int ITER = K / 32;
    for (int it = 0; it < ITER; ++it) {
        #pragma unroll
        for (int s = 0; s < 4; s++) {
            int idx = tid + 256 * s;
            int m = idx >> 3, kq = (idx & 7) * 4;
            float* p = &As[m * LDA + kq];
            p[0] = tf32r(ra[s].x); p[1] = tf32r(ra[s].y);
            p[2] = tf32r(ra[s].z); p[3] = tf32r(ra[s].w);
        }
        #pragma unroll
        for (int s = 0; s < 4; s++) {
            int idx = tid + 256 * s;
            int k = idx >> 5, n4 = (idx & 31) * 4;
            float* p = &Bs[k * LDB + n4];
            p[0] = tf32r(rb[s].x); p[1] = tf32r(rb[s].y);
            p[2] = tf32r(rb[s].z); p[3] = tf32r(rb[s].w);
        }
        __syncthreads();
        if (it + 1 < ITER) {
            int k0n = (it + 1) * 32;
            #pragma unroll
            for (int s = 0; s < 4; s++) {
                int idx = tid + 256 * s;
                int m = idx >> 3, kq = (idx & 7) * 4;
                ra[s] = *(const float4*)(A + (size_t)(m0 + m) * K + k0n + kq);
            }
            #pragma unroll
            for (int s = 0; s < 4; s++) {
                int idx = tid + 256 * s;
                int k = idx >> 5, n4 = (idx & 31) * 4;
                int kk = k0n + k;
                const float* bp = (kk < 2048) ? (Wrel + (size_t)kk * Dv)
                                              : (Wroot + (size_t)(kk - 2048) * Dv);
                rb[s] = *(const float4*)(bp + n0 + n4);
            }
        }
        #pragma unroll
        for (int ks = 0; ks < 4; ks++) {
            int kb = ks * 8;
            uint32_t af[4][4], bf[4][2];
            #pragma unroll
            for (int mt = 0; mt < 4; mt++) {
                int mr = wr * 64 + mt * 16;
                af[mt][0] = __float_as_uint(As[(mr + g)     * LDA + kb + tig]);
                af[mt][1] = __float_as_uint(As[(mr + g + 8) * LDA + kb + tig]);
                af[mt][2] = __float_as_uint(As[(mr + g)     * LDA + kb + tig + 4]);
                af[mt][3] = __float_as_uint(As[(mr + g + 8) * LDA + kb + tig + 4]);
            }
            #pragma unroll
            for (int nt = 0; nt < 4; nt++) {
                int nc = wc * 32 + nt * 8;
                bf[nt][0] = __float_as_uint(Bs[(kb + tig)     * LDB + nc + g]);
                bf[nt][1] = __float_as_uint(Bs[(kb + tig + 4) * LDB + nc + g]);
            }
            #pragma unroll
            for (int mt = 0; mt < 4; mt++)
                #pragma unroll
                for (int nt = 0; nt < 4; nt++)
                    mma8(acc[mt][nt], af[mt], bf[nt]);
        }
        __syncthreads();
    }
    #pragma unroll
    for (int mt = 0; mt < 4; mt++) {
        int mr = m0 + wr * 64 + mt * 16;
        #pragma unroll
        for (int nt = 0; nt < 4; nt++) {
            int nc = n0 + wc * 32 + nt * 8 + 2 * tig;
            float b0 = bias[nc], b1 = bias[nc + 1];
            float2 v0 = {acc[mt][nt][0] + b0, acc[mt][nt][1] + b1};
            float2 v1 = {acc[mt][nt][2] + b0, acc[mt][nt][3] + b1};
            *(float2*)(C + (size_t)(mr + g)     * Dv + nc) = v0;
            *(float2*)(C + (size_t)(mr + g + 8) * Dv + nc) = v1;
        }
    }
}

// Kernel 3: [q|k|v|skip] = ho [8192x512] @ W [512x2048] + b
__global__ __launch_bounds__(256) void gemm_qkvs(
    const float* __restrict__ Wq, const float* __restrict__ Wk,
    const float* __restrict__ Wv, const float* __restrict__ Ws,
    const float* __restrict__ bq, const float* __restrict__ bk,
    const float* __restrict__ bv, const float* __restrict__ bs)
{
    __shared__ float As[128 * LDA];
    __shared__ float Bs[32 * LDB];
    const float* A = g_ho;
    float* C = g_qkvs;
    const int K = Dv;
    int tid = threadIdx.x;
    int n0 = blockIdx.x * 128, m0 = blockIdx.y * 128;
    int wsel = n0 >> 9;
    const float* W  = (wsel == 0) ? Wq : (wsel == 1) ? Wk : (wsel == 2) ? Wv : Ws;
    const float* bb = (wsel == 0) ? bq : (wsel == 1) ? bk : (wsel == 2) ? bv : bs;
    int bc0 = n0 & 511;
    int wid = tid >> 5, lane = tid & 31;
    int wr = wid >> 2, wc = wid & 3;
    int g = lane >> 2, tig = lane & 3;
    float acc[4][4][4] = {};
    float4 ra[4], rb[4];

    #pragma unroll
    for (int s = 0; s < 4; s++) {
        int idx = tid + 256 * s;
        int m = idx >> 3, kq = (idx & 7) * 4;
        ra[s] = *(const float4*)(A + (size_t)(m0 + m) * K + kq);
    }
    #pragma unroll
    for (int s = 0; s < 4; s++) {
        int idx = tid + 256 * s;
        int k = idx >> 5, n4 = (idx & 31) * 4;
        rb[s] = *(const float4*)(W + (size_t)k * Dv + bc0 + n4);
    }

    const int ITER = K / 32;   // 16
    for (int it = 0; it < ITER; ++it) {
        #pragma unroll
        for (int s = 0; s < 4; s++) {
            int idx = tid + 256 * s;
            int m = idx >> 3, kq = (idx & 7) * 4;
            float* p = &As[m * LDA + kq];
            p[0] = tf32r(ra[s].x); p[1] = tf32r(ra[s].y);
            p[2] = tf32r(ra[s].z); p[3] = tf32r(ra[s].w);
        }
        #pragma unroll
        for (int s = 0; s < 4; s++) {
            int idx = tid + 256 * s;
            int k = idx >> 5, n4 = (idx & 31) * 4;
            float* p = &Bs[k * LDB + n4];
            p[0] = tf32r(rb[s].x); p[1] = tf32r(rb[s].y);
            p[2] = tf32r(rb[s].z); p[3] = tf32r(rb[s].w);
        }
        __syncthreads();
        if (it + 1 < ITER) {
            int k0n = (it + 1) * 32;
            #pragma unroll
            for (int s = 0; s < 4; s++) {
                int idx = tid + 256 * s;
                int m = idx >> 3, kq = (idx & 7) * 4;
                ra[s] = *(const float4*)(A + (size_t)(m0 + m) * K + k0n + kq);
            }
            #pragma unroll
            for (int s = 0; s < 4; s++) {
                int idx = tid + 256 * s;
                int k = idx >> 5, n4 = (idx & 31) * 4;
                rb[s] = *(const float4*)(W + (size_t)(k0n + k) * Dv + bc0 + n4);
            }
        }
        #pragma unroll
        for (int ks = 0; ks < 4; ks++) {
            int kb = ks * 8;
            uint32_t af[4][4], bf[4][2];
            #pragma unroll
            for (int mt = 0; mt < 4; mt++) {
                int mr = wr * 64 + mt * 16;
                af[mt][0] = __float_as_uint(As[(mr + g)     * LDA + kb + tig]);
                af[mt][1] = __float_as_uint(As[(mr + g + 8) * LDA + kb + tig]);
                af[mt][2] = __float_as_uint(As[(mr + g)     * LDA + kb + tig + 4]);
                af[mt][3] = __float_as_uint(As[(mr + g + 8) * LDA + kb + tig + 4]);
            }
            #pragma unroll
            for (int nt = 0; nt < 4; nt++) {
                int nc = wc * 32 + nt * 8;
                bf[nt][0] = __float_as_uint(Bs[(kb + tig)     * LDB + nc + g]);
                bf[nt][1] = __float_as_uint(Bs[(kb + tig + 4) * LDB + nc + g]);
            }
            #pragma unroll
            for (int mt = 0; mt < 4; mt++)
                #pragma unroll
                for (int nt = 0; nt < 4; nt++)
                    mma8(acc[mt][nt], af[mt], bf[nt]);
        }
        __syncthreads();
    }
    #pragma unroll
    for (int mt = 0; mt < 4; mt++) {
        int mr = m0 + wr * 64 + mt * 16;
        #pragma unroll
        for (int nt = 0; nt < 4; nt++) {
            int colw = wc * 32 + nt * 8 + 2 * tig;
            int nc = n0 + colw;            // global col in [0,2048)
            int bi = bc0 + colw;           // index into 512-wide bias
            float b0 = bb[bi], b1 = bb[bi + 1];
            float2 v0 = {acc[mt][nt][0] + b0, acc[mt][nt][1] + b1};
            float2 v1 = {acc[mt][nt][2] + b0, acc[mt][nt][3] + b1};
            *(float2*)(C + (size_t)(mr + g)     * QK + nc) = v0;
            *(float2*)(C + (size_t)(mr + g + 8) * QK + nc) = v1;
        }
    }
}

// ============================================================
// Kernel 4: per-node attention softmax + skip + leaky + residual + LN
// ============================================================
__global__ __launch_bounds__(256) void attn_kernel(
    const float* __restrict__ x,
    const int*   __restrict__ src,
    const int*   __restrict__ dst,
    int E,
    const float* __restrict__ gamma,
    const float* __restrict__ beta,
    float* __restrict__ out)
{
    int i = blockIdx.x;
    int t = threadIdx.x;
    __shared__ float q_s[512];
    __shared__ float logit[32];
    __shared__ float alpha[32];
    __shared__ int   s_src[32];
    __shared__ int   s_lo, s_nE;
    __shared__ float red1[8], red2[8];
    __shared__ float s_mu, s_rstd;
    const float* qkvs = g_qkvs;

    if (t == 0) {
        int lo = lower_bound_i(dst, E, i);
        int hi = lower_bound_i(dst, E, i + 1);
        s_lo = lo; int n = hi - lo; if (n > 32) n = 32; s_nE = n;
    }
    __syncthreads();
    int nE = s_nE, lo = s_lo;
    q_s[t]       = qkvs[(size_t)i * QK + t];
    q_s[t + 256] = qkvs[(size_t)i * QK + t + 256];
    if (t < nE) s_src[t] = src[lo + t];
    __syncthreads();

    int wid = t >> 5, lane = t & 31;
    for (int e = wid; e < nE; e += 8) {
        const float* kp = qkvs + (size_t)s_src[e] * QK + 512;
        float sum = 0.f;
        #pragma unroll
        for (int c = 0; c < 4; c++) {
            int d = c * 128 + lane * 4;
            float4 qa = *(const float4*)&q_s[d];
            float4 kb = *(const float4*)(kp + d);
            sum += qa.x*kb.x + qa.y*kb.y + qa.z*kb.z + qa.w*kb.w;
        }
        #pragma unroll
        for (int o = 16; o; o >>= 1) sum += __shfl_xor_sync(0xffffffffu, sum, o);
        if (lane == 0) logit[e] = sum * 0.04419417382415922f; // 1/sqrt(512)
    }
    __syncthreads();
    if (t == 0) {
        float mx = -INFINITY;
        for (int e = 0; e < nE; e++) mx = fmaxf(mx, logit[e]);
        if (nE == 0 || !isfinite(mx)) mx = 0.f;
        float den = 0.f;
        for (int e = 0; e < nE; e++) { float ex = expf(logit[e] - mx); alpha[e] = ex; den += ex; }
        float inv = 1.f / fmaxf(den, 1e-16f);
        for (int e = 0; e < nE; e++) alpha[e] *= inv;
    }
    __syncthreads();

    int d0 = t * 2;
    float acc0 = 0.f, acc1 = 0.f;
    for (int e = 0; e < nE; e++) {
        float a = alpha[e];
        float2 v = *(const float2*)(qkvs + (size_t)s_src[e] * QK + 1024 + d0);
        acc0 += a * v.x; acc1 += a * v.y;
    }
    float2 sk = *(const float2*)(qkvs + (size_t)i * QK + 1536 + d0);
    float h0 = acc0 + sk.x, h1 = acc1 + sk.y;
    h0 = h0 > 0.f ? h0 : 0.01f * h0;
    h1 = h1 > 0.f ? h1 : 0.01f * h1;
    float2 xv = *(const float2*)(x + (size_t)i * Dv + d0);
    float o0 = xv.x + h0, o1 = xv.y + h1;

    float s1 = o0 + o1, s2 = o0*o0 + o1*o1;
    #pragma unroll
    for (int o = 16; o; o >>= 1) {
        s1 += __shfl_xor_sync(0xffffffffu, s1, o);
        s2 += __shfl_xor_sync(0xffffffffu, s2, o);
    }
    if (lane == 0) { red1[wid] = s1; red2[wid] = s2; }
    __syncthreads();
    if (t == 0) {
        float S1 = 0.f, S2 = 0.f;
        #pragma unroll
        for (int w = 0; w < 8; w++) { S1 += red1[w]; S2 += red2[w]; }
        float mu = S1 / 512.f;
        float var = S2 / 512.f - mu * mu;
        s_mu = mu; s_rstd = rsqrtf(var + 1e-5f);
    }
    __syncthreads();
    float mu = s_mu, rs = s_rstd;
    float2 ov;
    ov.x = (o0 - mu) * rs * gamma[d0]     + beta[d0];
    ov.y = (o1 - mu) * rs * gamma[d0 + 1] + beta[d0 + 1];
    *(float2*)(out + (size_t)i * Dv + d0) = ov;
}

// scalar loss output (always 0 in eval path)
__global__ void tail_kernel(float* out, int out_size) {
    int idx = Nn * Dv + threadIdx.x;
    if (idx < out_size) out[idx] = 0.f;
}

extern "C" void kernel_launch(void* const* d_in, const int* in_sizes, int n_in,
                              void* d_out, int out_size) {
    const float* x     = (const float*)d_in[0];
    const int*   ei    = (const int*)  d_in[1];
    const int*   et    = (const int*)  d_in[2];
    const float* Wrel  = (const float*)d_in[3];
    const float* Wroot = (const float*)d_in[4];
    const float* brg   = (const float*)d_in[5];
    const float* Wq    = (const float*)d_in[6];
    const float* bq    = (const float*)d_in[7];
    const float* Wk    = (const float*)d_in[8];
    const float* bk    = (const float*)d_in[9];
    const float* Wv    = (const float*)d_in[10];
    const float* bv    = (const float*)d_in[11];
    const float* Wsk   = (const float*)d_in[12];
    const float* bsk   = (const float*)d_in[13];
    const float* gamma = (const float*)d_in[14];
    const float* beta  = (const float*)d_in[15];
    float* out = (float*)d_out;

    int E = in_sizes[2];
    const int* src = ei;
    const int* dst = ei + E;

    agg_kernel<<<Nn, 128>>>(x, src, dst, et, E);
    gemm_rgcn<<<dim3(Dv / 128, Nn / 128), 256>>>(Wrel, Wroot, brg);
    gemm_qkvs<<<dim3(QK / 128, Nn / 128), 256>>>(Wq, Wk, Wv, Wsk, bq, bk, bv, bsk);
    attn_kernel<<<Nn, 256>>>(x, src, dst, E, gamma, beta, out);
    if (out_size > Nn * Dv) tail_kernel<<<1, 256>>>(out, out_size);
}